// round 1
// baseline (speedup 1.0000x reference)
#include <cuda_runtime.h>
#include <cstdint>
#include <cstddef>

#define EPS_ 1e-5f
#define KADA 0.1f

// ---------------------------------------------------------------------------
// Persistent scratch (device globals: the sanctioned no-alloc workaround)
// ---------------------------------------------------------------------------
__device__ float d_h1[(size_t)2 * 96 * 96 * 96 * 16];   // 113 MB
__device__ float d_h2[(size_t)2 * 48 * 48 * 48 * 32];   // 28 MB
__device__ float d_h3[(size_t)2 * 48 * 48 * 48 * 32];   // 28 MB
__device__ float d_h4[(size_t)2 * 24 * 24 * 24 * 64];   // 7 MB
__device__ float d_h5[(size_t)2 * 24 * 24 * 24 * 64];   // 7 MB
__device__ float d_m2[2 * 48 * 48 * 48];
__device__ float d_m3[2 * 24 * 24 * 24];
__device__ float d_pool[2 * 64];

// ---------------------------------------------------------------------------
// Mask downsample: m_out[o] = max over 3^3 window at stride 2, pad 1
// ---------------------------------------------------------------------------
template <int GIN, int GOUT>
__global__ void downsample_kernel(const float* __restrict__ mi, float* __restrict__ mo) {
    int i = blockIdx.x * blockDim.x + threadIdx.x;
    const int n = 2 * GOUT * GOUT * GOUT;
    if (i >= n) return;
    int x = i % GOUT; int t = i / GOUT;
    int y = t % GOUT; t /= GOUT;
    int z = t % GOUT; int b = t / GOUT;
    float v = 0.f;
    for (int kd = 0; kd < 3; kd++) {
        int iz = 2 * z + kd - 1; if (iz < 0 || iz >= GIN) continue;
        for (int kh = 0; kh < 3; kh++) {
            int iy = 2 * y + kh - 1; if (iy < 0 || iy >= GIN) continue;
            for (int kw = 0; kw < 3; kw++) {
                int ix = 2 * x + kw - 1; if (ix < 0 || ix >= GIN) continue;
                v = fmaxf(v, mi[((b * GIN + iz) * GIN + iy) * GIN + ix]);
            }
        }
    }
    mo[i] = v;
}

// ---------------------------------------------------------------------------
// Layer 1: SubMConv3d 1->16 on 96^3, fused AdaNorm+ReLU+mask.
// Thread per output voxel; 95% of threads just write zeros.
// ---------------------------------------------------------------------------
__global__ void l1_kernel(const float* __restrict__ x, const float* __restrict__ mask,
                          const float* __restrict__ w1, const float* __restrict__ b1,
                          const float* __restrict__ g1) {
    __shared__ float ws[27 * 16];
    __shared__ float bs[16];
    __shared__ float gs[16];
    for (int j = threadIdx.x; j < 432; j += blockDim.x) ws[j] = w1[j];
    if (threadIdx.x < 16) { bs[threadIdx.x] = b1[threadIdx.x]; gs[threadIdx.x] = g1[threadIdx.x]; }
    __syncthreads();

    int i = blockIdx.x * blockDim.x + threadIdx.x;   // exact grid: 2*96^3 / 128
    int xo = i % 96; int t = i / 96;
    int yo = t % 96; t /= 96;
    int zo = t % 96; int b = t / 96;

    float m = mask[i];
    float* out = d_h1 + (size_t)i * 16;
    float4* out4 = reinterpret_cast<float4*>(out);
    if (m == 0.f) {
        float4 z4 = make_float4(0.f, 0.f, 0.f, 0.f);
        out4[0] = z4; out4[1] = z4; out4[2] = z4; out4[3] = z4;
        return;
    }
    float acc[16];
#pragma unroll
    for (int c = 0; c < 16; c++) acc[c] = 0.f;

    for (int kd = 0; kd < 3; kd++) {
        int iz = zo + kd - 1; if (iz < 0 || iz >= 96) continue;
        for (int kh = 0; kh < 3; kh++) {
            int iy = yo + kh - 1; if (iy < 0 || iy >= 96) continue;
            for (int kw = 0; kw < 3; kw++) {
                int ix = xo + kw - 1; if (ix < 0 || ix >= 96) continue;
                float xv = x[((b * 96 + iz) * 96 + iy) * 96 + ix];
                if (xv != 0.f) {
                    int wb = ((kd * 3 + kh) * 3 + kw) * 16;
#pragma unroll
                    for (int c = 0; c < 16; c++) acc[c] += xv * ws[wb + c];
                }
            }
        }
    }
    // bias + AdaNorm + ReLU
    float v[16]; float s = 0.f;
#pragma unroll
    for (int c = 0; c < 16; c++) { v[c] = acc[c] + bs[c]; s += v[c]; }
    float mean = s * (1.f / 16.f);
    float s2 = 0.f;
#pragma unroll
    for (int c = 0; c < 16; c++) { float d = v[c] - mean; s2 += d * d; }
    float r = rsqrtf(s2 * (1.f / 16.f) + EPS_);
#pragma unroll
    for (int q = 0; q < 4; q++) {
        float4 o4;
        float xn0 = (v[q * 4 + 0] - mean) * r; o4.x = fmaxf(gs[q * 4 + 0] * (1.f - KADA * xn0) * xn0, 0.f);
        float xn1 = (v[q * 4 + 1] - mean) * r; o4.y = fmaxf(gs[q * 4 + 1] * (1.f - KADA * xn1) * xn1, 0.f);
        float xn2 = (v[q * 4 + 2] - mean) * r; o4.z = fmaxf(gs[q * 4 + 2] * (1.f - KADA * xn2) * xn2, 0.f);
        float xn3 = (v[q * 4 + 3] - mean) * r; o4.w = fmaxf(gs[q * 4 + 3] * (1.f - KADA * xn3) * xn3, 0.f);
        out4[q] = o4;
    }
}

// ---------------------------------------------------------------------------
// Layer 2: SparseConv3d s=2, 16->32, 96^3 -> 48^3, fused AdaNorm+ReLU+mask.
// Warp per output voxel, lane = output channel.
// The m1 tap check is warp-uniform => true branch skip of inactive taps (~95%).
// ---------------------------------------------------------------------------
__global__ void l2_kernel(const float* __restrict__ mask, const float* __restrict__ w2,
                          const float* __restrict__ b2, const float* __restrict__ g2) {
    extern __shared__ float sm[];
    float* ws = sm;                 // 13824 floats
    float* bs = sm + 13824;         // 32
    float* gs = bs + 32;            // 32
    for (int j = threadIdx.x; j < 13824; j += blockDim.x) ws[j] = w2[j];
    if (threadIdx.x < 32) { bs[threadIdx.x] = b2[threadIdx.x]; gs[threadIdx.x] = g2[threadIdx.x]; }
    __syncthreads();

    int lane = threadIdx.x & 31;
    int warp = threadIdx.x >> 5;
    int gwarp = blockIdx.x * (blockDim.x >> 5) + warp;
    int nwarps = gridDim.x * (blockDim.x >> 5);

    for (int v = gwarp; v < 2 * 48 * 48 * 48; v += nwarps) {
        int xo = v % 48; int t = v / 48;
        int yo = t % 48; t /= 48;
        int zo = t % 48; int b = t / 48;

        float mo = d_m2[v];
        float* out = d_h2 + (size_t)v * 32;
        if (mo == 0.f) { out[lane] = 0.f; continue; }

        float acc = 0.f;
        for (int kd = 0; kd < 3; kd++) {
            int iz = 2 * zo + kd - 1; if (iz < 0 || iz >= 96) continue;
            for (int kh = 0; kh < 3; kh++) {
                int iy = 2 * yo + kh - 1; if (iy < 0 || iy >= 96) continue;
                for (int kw = 0; kw < 3; kw++) {
                    int ix = 2 * xo + kw - 1; if (ix < 0 || ix >= 96) continue;
                    int ii = ((b * 96 + iz) * 96 + iy) * 96 + ix;
                    float m1v = mask[ii];
                    if (m1v != 0.f) {   // warp-uniform
                        const float4* ip4 = reinterpret_cast<const float4*>(d_h1 + (size_t)ii * 16);
                        int wb = ((kd * 3 + kh) * 3 + kw) * 512 + lane;
#pragma unroll
                        for (int q = 0; q < 4; q++) {
                            float4 a = ip4[q];
                            acc += a.x * ws[wb + (q * 4 + 0) * 32];
                            acc += a.y * ws[wb + (q * 4 + 1) * 32];
                            acc += a.z * ws[wb + (q * 4 + 2) * 32];
                            acc += a.w * ws[wb + (q * 4 + 3) * 32];
                        }
                    }
                }
            }
        }
        float vv = acc + bs[lane];
        // warp AdaNorm over 32 channels
        float s = vv;
#pragma unroll
        for (int off = 16; off > 0; off >>= 1) s += __shfl_xor_sync(0xffffffffu, s, off);
        float mean = s * (1.f / 32.f);
        float d = vv - mean;
        float s2 = d * d;
#pragma unroll
        for (int off = 16; off > 0; off >>= 1) s2 += __shfl_xor_sync(0xffffffffu, s2, off);
        float r = rsqrtf(s2 * (1.f / 32.f) + EPS_);
        float xn = d * r;
        out[lane] = fmaxf(gs[lane] * (1.f - KADA * xn) * xn, 0.f);
    }
}

// ---------------------------------------------------------------------------
// Generic conv (layers 3/4/5): thread = 2 adjacent-x output voxels x 32 out-ch.
// Weights staged in shared per kd slice. Writes (conv + bias) * m_out.
// ---------------------------------------------------------------------------
template <int CIN, int GIN, int GOUT, int STRIDE>
__global__ void conv_kernel(const float* __restrict__ in, const float* __restrict__ w,
                            const float* __restrict__ bias, const float* __restrict__ mout,
                            float* __restrict__ out, int cout_total) {
    extern __shared__ float ws[];   // 9*CIN*32 floats
    const int cobase = blockIdx.y * 32;
    int tid = threadIdx.x;
    int pid = blockIdx.x * blockDim.x + tid;    // exact grid: pairs / 128
    const int GX2 = GOUT / 2;
    int xp = pid % GX2; int t = pid / GX2;
    int yo = t % GOUT; t /= GOUT;
    int zo = t % GOUT; int b = t / GOUT;
    int x0 = xp * 2;

    size_t vox0 = ((size_t)(b * GOUT + zo) * GOUT + yo) * GOUT + x0;
    float m0 = mout[vox0], m1_ = mout[vox0 + 1];
    bool act = (m0 != 0.f) || (m1_ != 0.f);

    float acc0[32], acc1[32];
#pragma unroll
    for (int c = 0; c < 32; c++) { acc0[c] = 0.f; acc1[c] = 0.f; }

    for (int kd = 0; kd < 3; kd++) {
        __syncthreads();
        {
            const int n = 9 * CIN * 32;
            for (int j = tid; j < n; j += blockDim.x) {
                int co = j & 31;
                int rest = j >> 5;             // = khw*CIN + ci
                int ci = rest % CIN;
                int khw = rest / CIN;
                ws[j] = w[((size_t)(kd * 9 + khw) * CIN + ci) * cout_total + cobase + co];
            }
        }
        __syncthreads();

        int iz = zo * STRIDE + kd - 1;
        if (act && iz >= 0 && iz < GIN) {
            for (int kh = 0; kh < 3; kh++) {
                int iy = yo * STRIDE + kh - 1; if (iy < 0 || iy >= GIN) continue;
                size_t rowbase = ((size_t)(b * GIN + iz) * GIN + iy) * GIN;
                for (int kw = 0; kw < 3; kw++) {
                    int ix0 = x0 * STRIDE + kw - 1;
                    int ix1 = ix0 + STRIDE;
                    bool i0 = (ix0 >= 0) && (ix0 < GIN);
                    bool i1 = (ix1 >= 0) && (ix1 < GIN);
                    const float4* p04 = reinterpret_cast<const float4*>(in + (rowbase + (i0 ? ix0 : 0)) * CIN);
                    const float4* p14 = reinterpret_cast<const float4*>(in + (rowbase + (i1 ? ix1 : 0)) * CIN);
                    const float* wrow = ws + (kh * 3 + kw) * CIN * 32;
                    const float4 z4 = make_float4(0.f, 0.f, 0.f, 0.f);
#pragma unroll 4
                    for (int ci4 = 0; ci4 < CIN / 4; ci4++) {
                        float4 a0 = i0 ? p04[ci4] : z4;
                        float4 a1 = i1 ? p14[ci4] : z4;
                        const float* wr = wrow + ci4 * 128;
#pragma unroll
                        for (int co = 0; co < 32; co++) { float wv = wr[co];      acc0[co] += a0.x * wv; acc1[co] += a1.x * wv; }
#pragma unroll
                        for (int co = 0; co < 32; co++) { float wv = wr[32 + co]; acc0[co] += a0.y * wv; acc1[co] += a1.y * wv; }
#pragma unroll
                        for (int co = 0; co < 32; co++) { float wv = wr[64 + co]; acc0[co] += a0.z * wv; acc1[co] += a1.z * wv; }
#pragma unroll
                        for (int co = 0; co < 32; co++) { float wv = wr[96 + co]; acc0[co] += a0.w * wv; acc1[co] += a1.w * wv; }
                    }
                }
            }
        }
    }

    const float4 z4 = make_float4(0.f, 0.f, 0.f, 0.f);
    float4* o0 = reinterpret_cast<float4*>(out + vox0 * cout_total + cobase);
    float4* o1 = reinterpret_cast<float4*>(out + (vox0 + 1) * cout_total + cobase);
    if (m0 != 0.f) {
#pragma unroll
        for (int q = 0; q < 8; q++) {
            float4 rr;
            rr.x = acc0[q * 4 + 0] + bias[cobase + q * 4 + 0];
            rr.y = acc0[q * 4 + 1] + bias[cobase + q * 4 + 1];
            rr.z = acc0[q * 4 + 2] + bias[cobase + q * 4 + 2];
            rr.w = acc0[q * 4 + 3] + bias[cobase + q * 4 + 3];
            o0[q] = rr;
        }
    } else {
#pragma unroll
        for (int q = 0; q < 8; q++) o0[q] = z4;
    }
    if (m1_ != 0.f) {
#pragma unroll
        for (int q = 0; q < 8; q++) {
            float4 rr;
            rr.x = acc1[q * 4 + 0] + bias[cobase + q * 4 + 0];
            rr.y = acc1[q * 4 + 1] + bias[cobase + q * 4 + 1];
            rr.z = acc1[q * 4 + 2] + bias[cobase + q * 4 + 2];
            rr.w = acc1[q * 4 + 3] + bias[cobase + q * 4 + 3];
            o1[q] = rr;
        }
    } else {
#pragma unroll
        for (int q = 0; q < 8; q++) o1[q] = z4;
    }
}

// ---------------------------------------------------------------------------
// In-place AdaNorm + ReLU over the channel axis (zero rows stay zero)
// ---------------------------------------------------------------------------
template <int C>
__global__ void adanorm_kernel(float* __restrict__ h, const float* __restrict__ g, int nvox) {
    int i = blockIdx.x * blockDim.x + threadIdx.x;
    if (i >= nvox) return;
    float4* p = reinterpret_cast<float4*>(h + (size_t)i * C);
    float v[C];
#pragma unroll
    for (int q = 0; q < C / 4; q++) {
        float4 a = p[q];
        v[q * 4 + 0] = a.x; v[q * 4 + 1] = a.y; v[q * 4 + 2] = a.z; v[q * 4 + 3] = a.w;
    }
    float s = 0.f;
#pragma unroll
    for (int c = 0; c < C; c++) s += v[c];
    float mean = s * (1.f / C);
    float s2 = 0.f;
#pragma unroll
    for (int c = 0; c < C; c++) { float d = v[c] - mean; s2 += d * d; }
    float r = rsqrtf(s2 * (1.f / C) + EPS_);
#pragma unroll
    for (int q = 0; q < C / 4; q++) {
        float4 a;
        float xn;
        xn = (v[q * 4 + 0] - mean) * r; a.x = fmaxf(g[q * 4 + 0] * (1.f - KADA * xn) * xn, 0.f);
        xn = (v[q * 4 + 1] - mean) * r; a.y = fmaxf(g[q * 4 + 1] * (1.f - KADA * xn) * xn, 0.f);
        xn = (v[q * 4 + 2] - mean) * r; a.z = fmaxf(g[q * 4 + 2] * (1.f - KADA * xn) * xn, 0.f);
        xn = (v[q * 4 + 3] - mean) * r; a.w = fmaxf(g[q * 4 + 3] * (1.f - KADA * xn) * xn, 0.f);
        p[q] = a;
    }
}

// ---------------------------------------------------------------------------
// Global masked max pool over 24^3 voxels -> d_pool[2][64]
// ---------------------------------------------------------------------------
__global__ void pool_kernel() {
    int b = blockIdx.x;
    int c = threadIdx.x & 63;
    int grp = threadIdx.x >> 6;   // 16 groups
    float best = -3.0e38f;
    for (int v = grp; v < 13824; v += 16) {
        float m = d_m3[b * 13824 + v];
        float hv = d_h5[((size_t)(b * 13824 + v)) * 64 + c];
        best = fmaxf(best, m > 0.f ? hv : -3.0e38f);
    }
    __shared__ float red[1024];
    red[threadIdx.x] = best;
    __syncthreads();
    for (int s = 8; s > 0; s >>= 1) {
        if (grp < s) red[grp * 64 + c] = fmaxf(red[grp * 64 + c], red[(grp + s) * 64 + c]);
        __syncthreads();
    }
    if (grp == 0) d_pool[b * 64 + c] = red[c];
}

// ---------------------------------------------------------------------------
// Head: pooled @ wh + bh -> AdaNorm -> ReLU
// ---------------------------------------------------------------------------
__global__ void head_kernel(const float* __restrict__ wh, const float* __restrict__ bh,
                            const float* __restrict__ gh, float* __restrict__ out) {
    int t = threadIdx.x;          // 128 threads: b = t/64, f = t%64
    int b = t >> 6;
    int f = t & 63;
    float s = bh[f];
    for (int ci = 0; ci < 64; ci++) s += d_pool[b * 64 + ci] * wh[ci * 64 + f];
    __shared__ float sh[128];
    sh[t] = s;
    __syncthreads();
    float sum = 0.f;
    for (int j = 0; j < 64; j++) sum += sh[b * 64 + j];
    float mean = sum * (1.f / 64.f);
    float var = 0.f;
    for (int j = 0; j < 64; j++) { float d = sh[b * 64 + j] - mean; var += d * d; }
    float r = rsqrtf(var * (1.f / 64.f) + EPS_);
    float xn = (s - mean) * r;
    out[t] = fmaxf(gh[f] * (1.f - KADA * xn) * xn, 0.f);
}

// ---------------------------------------------------------------------------
// Launch
// ---------------------------------------------------------------------------
extern "C" void kernel_launch(void* const* d_in, const int* in_sizes, int n_in,
                              void* d_out, int out_size) {
    const float* x    = (const float*)d_in[0];
    const float* mask = (const float*)d_in[1];
    const float* w1 = (const float*)d_in[2];
    const float* b1 = (const float*)d_in[3];
    const float* g1 = (const float*)d_in[4];
    const float* w2 = (const float*)d_in[5];
    const float* b2 = (const float*)d_in[6];
    const float* g2 = (const float*)d_in[7];
    const float* w3 = (const float*)d_in[8];
    const float* b3 = (const float*)d_in[9];
    const float* g3 = (const float*)d_in[10];
    const float* w4 = (const float*)d_in[11];
    const float* b4 = (const float*)d_in[12];
    const float* g4 = (const float*)d_in[13];
    const float* w5 = (const float*)d_in[14];
    const float* b5 = (const float*)d_in[15];
    const float* g5 = (const float*)d_in[16];
    const float* wh = (const float*)d_in[17];
    const float* bh = (const float*)d_in[18];
    const float* gh = (const float*)d_in[19];
    float* out = (float*)d_out;

    // dynamic smem limits (>48 KB kernels)
    cudaFuncSetAttribute(l2_kernel, cudaFuncAttributeMaxDynamicSharedMemorySize, 56 * 1024);
    cudaFuncSetAttribute(conv_kernel<64, 24, 24, 1>, cudaFuncAttributeMaxDynamicSharedMemorySize, 74 * 1024);

    // device symbol addresses for conv kernel arguments
    void *ph2, *ph3, *ph4, *ph5, *pm2, *pm3;
    cudaGetSymbolAddress(&ph2, d_h2);
    cudaGetSymbolAddress(&ph3, d_h3);
    cudaGetSymbolAddress(&ph4, d_h4);
    cudaGetSymbolAddress(&ph5, d_h5);
    cudaGetSymbolAddress(&pm2, d_m2);
    cudaGetSymbolAddress(&pm3, d_m3);

    // masks
    downsample_kernel<96, 48><<<(2 * 48 * 48 * 48 + 255) / 256, 256>>>(mask, (float*)pm2);
    downsample_kernel<48, 24><<<(2 * 24 * 24 * 24 + 255) / 256, 256>>>((const float*)pm2, (float*)pm3);

    // layer 1 (fused)
    l1_kernel<<<2 * 96 * 96 * 96 / 128, 128>>>(x, mask, w1, b1, g1);

    // layer 2 (fused, warp-sparse)
    l2_kernel<<<592, 256, (13824 + 64) * 4>>>(mask, w2, b2, g2);

    // layer 3: 48^3, 32->32, stride 1
    conv_kernel<32, 48, 48, 1><<<dim3(864, 1), 128, 9 * 32 * 32 * 4>>>(
        (const float*)ph2, w3, b3, (const float*)pm2, (float*)ph3, 32);
    adanorm_kernel<32><<<(2 * 48 * 48 * 48 + 255) / 256, 256>>>((float*)ph3, g3, 2 * 48 * 48 * 48);

    // layer 4: 48^3 -> 24^3, 32->64, stride 2
    conv_kernel<32, 48, 24, 2><<<dim3(108, 2), 128, 9 * 32 * 32 * 4>>>(
        (const float*)ph3, w4, b4, (const float*)pm3, (float*)ph4, 64);
    adanorm_kernel<64><<<108, 256>>>((float*)ph4, g4, 2 * 24 * 24 * 24);

    // layer 5: 24^3, 64->64, stride 1
    conv_kernel<64, 24, 24, 1><<<dim3(108, 2), 128, 9 * 64 * 32 * 4>>>(
        (const float*)ph4, w5, b5, (const float*)pm3, (float*)ph5, 64);
    adanorm_kernel<64><<<108, 256>>>((float*)ph5, g5, 2 * 24 * 24 * 24);

    // pool + head
    pool_kernel<<<2, 1024>>>();
    head_kernel<<<1, 128>>>(wh, bh, gh, out);
}

// round 6
// speedup vs baseline: 1.1372x; 1.1372x over previous
#include <cuda_runtime.h>
#include <cstdint>
#include <cstddef>

#define EPS_ 1e-5f
#define KADA 0.1f

typedef unsigned long long ull;

// packed f32x2 helpers (FFMA2 path — sm_103a)
__device__ __forceinline__ ull pack2(float lo, float hi) {
    ull r; asm("mov.b64 %0, {%1, %2};" : "=l"(r) : "f"(lo), "f"(hi)); return r;
}
__device__ __forceinline__ void unpack2(ull v, float& lo, float& hi) {
    asm("mov.b64 {%0, %1}, %2;" : "=f"(lo), "=f"(hi) : "l"(v));
}
__device__ __forceinline__ ull fma2(ull a, ull b, ull c) {
    ull d; asm("fma.rn.f32x2 %0, %1, %2, %3;" : "=l"(d) : "l"(a), "l"(b), "l"(c)); return d;
}

// ---------------------------------------------------------------------------
// Persistent scratch
// ---------------------------------------------------------------------------
__device__ float d_h1[(size_t)2 * 96 * 96 * 96 * 16];   // only active sites valid
__device__ float d_h2[(size_t)2 * 48 * 48 * 48 * 32];
__device__ float d_h3[(size_t)2 * 48 * 48 * 48 * 32];
__device__ float d_h4[(size_t)2 * 24 * 24 * 24 * 64];
__device__ float d_h5[(size_t)2 * 24 * 24 * 24 * 64];
__device__ float d_m2[2 * 48 * 48 * 48];
__device__ float d_m3[2 * 24 * 24 * 24];
__device__ float d_pool[2 * 64];

// ---------------------------------------------------------------------------
// Mask downsample
// ---------------------------------------------------------------------------
template <int GIN, int GOUT>
__global__ void downsample_kernel(const float* __restrict__ mi, float* __restrict__ mo) {
    int i = blockIdx.x * blockDim.x + threadIdx.x;
    const int n = 2 * GOUT * GOUT * GOUT;
    if (i >= n) return;
    int x = i % GOUT; int t = i / GOUT;
    int y = t % GOUT; t /= GOUT;
    int z = t % GOUT; int b = t / GOUT;
    float v = 0.f;
    for (int kd = 0; kd < 3; kd++) {
        int iz = 2 * z + kd - 1; if (iz < 0 || iz >= GIN) continue;
        for (int kh = 0; kh < 3; kh++) {
            int iy = 2 * y + kh - 1; if (iy < 0 || iy >= GIN) continue;
            for (int kw = 0; kw < 3; kw++) {
                int ix = 2 * x + kw - 1; if (ix < 0 || ix >= GIN) continue;
                v = fmaxf(v, mi[((b * GIN + iz) * GIN + iy) * GIN + ix]);
            }
        }
    }
    mo[i] = v;
}

// ---------------------------------------------------------------------------
// Layer 1: SubMConv3d 1->16, fused AdaNorm+ReLU. Only ACTIVE voxels write
// (inactive sites of d_h1 are never read downstream).
// ---------------------------------------------------------------------------
__global__ void l1_kernel(const float* __restrict__ x, const float* __restrict__ mask,
                          const float* __restrict__ w1, const float* __restrict__ b1,
                          const float* __restrict__ g1) {
    __shared__ float ws[27 * 16];
    __shared__ float bs[16];
    __shared__ float gs[16];
    for (int j = threadIdx.x; j < 432; j += blockDim.x) ws[j] = w1[j];
    if (threadIdx.x < 16) { bs[threadIdx.x] = b1[threadIdx.x]; gs[threadIdx.x] = g1[threadIdx.x]; }
    __syncthreads();

    int i = blockIdx.x * blockDim.x + threadIdx.x;
    int xo = i % 96; int t = i / 96;
    int yo = t % 96; t /= 96;
    int zo = t % 96; int b = t / 96;

    float m = mask[i];
    if (m == 0.f) return;                    // inactive: nothing to do

    float acc[16];
#pragma unroll
    for (int c = 0; c < 16; c++) acc[c] = 0.f;

    for (int kd = 0; kd < 3; kd++) {
        int iz = zo + kd - 1; if (iz < 0 || iz >= 96) continue;
        for (int kh = 0; kh < 3; kh++) {
            int iy = yo + kh - 1; if (iy < 0 || iy >= 96) continue;
            for (int kw = 0; kw < 3; kw++) {
                int ix = xo + kw - 1; if (ix < 0 || ix >= 96) continue;
                float xv = x[((b * 96 + iz) * 96 + iy) * 96 + ix];
                if (xv != 0.f) {
                    int wb = ((kd * 3 + kh) * 3 + kw) * 16;
#pragma unroll
                    for (int c = 0; c < 16; c++) acc[c] += xv * ws[wb + c];
                }
            }
        }
    }
    float v[16]; float s = 0.f;
#pragma unroll
    for (int c = 0; c < 16; c++) { v[c] = acc[c] + bs[c]; s += v[c]; }
    float mean = s * (1.f / 16.f);
    float s2 = 0.f;
#pragma unroll
    for (int c = 0; c < 16; c++) { float d = v[c] - mean; s2 += d * d; }
    float r = rsqrtf(s2 * (1.f / 16.f) + EPS_);
    float4* out4 = reinterpret_cast<float4*>(d_h1 + (size_t)i * 16);
#pragma unroll
    for (int q = 0; q < 4; q++) {
        float4 o4;
        float xn0 = (v[q * 4 + 0] - mean) * r; o4.x = fmaxf(gs[q * 4 + 0] * (1.f - KADA * xn0) * xn0, 0.f);
        float xn1 = (v[q * 4 + 1] - mean) * r; o4.y = fmaxf(gs[q * 4 + 1] * (1.f - KADA * xn1) * xn1, 0.f);
        float xn2 = (v[q * 4 + 2] - mean) * r; o4.z = fmaxf(gs[q * 4 + 2] * (1.f - KADA * xn2) * xn2, 0.f);
        float xn3 = (v[q * 4 + 3] - mean) * r; o4.w = fmaxf(gs[q * 4 + 3] * (1.f - KADA * xn3) * xn3, 0.f);
        out4[q] = o4;
    }
}

// ---------------------------------------------------------------------------
// Layer 2: SparseConv3d s=2, 16->32, fused AdaNorm+ReLU.
// Warp per output voxel, lane = cout. Active taps found with ONE parallel
// mask load + ballot (E[active taps] ~= 1.35 of 27).
// ---------------------------------------------------------------------------
__global__ void l2_kernel(const float* __restrict__ mask, const float* __restrict__ w2,
                          const float* __restrict__ b2, const float* __restrict__ g2) {
    extern __shared__ float sm[];
    float* ws = sm;                 // 13824 floats [tap(27)][ci(16)][co(32)]
    float* bs = sm + 13824;
    float* gs = bs + 32;
    for (int j = threadIdx.x; j < 13824; j += blockDim.x) ws[j] = w2[j];
    if (threadIdx.x < 32) { bs[threadIdx.x] = b2[threadIdx.x]; gs[threadIdx.x] = g2[threadIdx.x]; }
    __syncthreads();

    int lane = threadIdx.x & 31;
    int warp = threadIdx.x >> 5;
    int gwarp = blockIdx.x * (blockDim.x >> 5) + warp;
    int nwarps = gridDim.x * (blockDim.x >> 5);

    // lane -> tap decomposition (lanes 27..31 idle in discovery)
    int kd = lane / 9, kh = (lane / 3) % 3, kw = lane % 3;

    for (int v = gwarp; v < 2 * 48 * 48 * 48; v += nwarps) {
        int xo = v % 48; int t = v / 48;
        int yo = t % 48; t /= 48;
        int zo = t % 48; int b = t / 48;

        float mo = d_m2[v];
        float* out = d_h2 + (size_t)v * 32;
        if (mo == 0.f) { out[lane] = 0.f; continue; }

        int iz = 2 * zo + kd - 1, iy = 2 * yo + kh - 1, ix = 2 * xo + kw - 1;
        bool inb = (lane < 27) && (unsigned)iz < 96u && (unsigned)iy < 96u && (unsigned)ix < 96u;
        int ii = ((b * 96 + iz) * 96 + iy) * 96 + ix;
        float mv = inb ? mask[ii] : 0.f;
        unsigned bits = __ballot_sync(0xffffffffu, mv != 0.f);

        float acc = 0.f;
        while (bits) {
            int tap = __ffs(bits) - 1; bits &= bits - 1;
            int it = __shfl_sync(0xffffffffu, ii, tap);
            const float4* ip4 = reinterpret_cast<const float4*>(d_h1 + (size_t)it * 16);
            const float* wt = ws + tap * 512 + lane;
            float4 a0 = ip4[0], a1 = ip4[1], a2 = ip4[2], a3 = ip4[3];
            acc += a0.x * wt[0 * 32];  acc += a0.y * wt[1 * 32];
            acc += a0.z * wt[2 * 32];  acc += a0.w * wt[3 * 32];
            acc += a1.x * wt[4 * 32];  acc += a1.y * wt[5 * 32];
            acc += a1.z * wt[6 * 32];  acc += a1.w * wt[7 * 32];
            acc += a2.x * wt[8 * 32];  acc += a2.y * wt[9 * 32];
            acc += a2.z * wt[10 * 32]; acc += a2.w * wt[11 * 32];
            acc += a3.x * wt[12 * 32]; acc += a3.y * wt[13 * 32];
            acc += a3.z * wt[14 * 32]; acc += a3.w * wt[15 * 32];
        }
        float vv = acc + bs[lane];
        float s = vv;
#pragma unroll
        for (int off = 16; off > 0; off >>= 1) s += __shfl_xor_sync(0xffffffffu, s, off);
        float mean = s * (1.f / 32.f);
        float d = vv - mean;
        float s2 = d * d;
#pragma unroll
        for (int off = 16; off > 0; off >>= 1) s2 += __shfl_xor_sync(0xffffffffu, s2, off);
        float r = rsqrtf(s2 * (1.f / 32.f) + EPS_);
        float xn = d * r;
        out[lane] = fmaxf(gs[lane] * (1.f - KADA * xn) * xn, 0.f);
    }
}

// ---------------------------------------------------------------------------
// Generic conv (L3/L4/L5) with FFMA2: thread = 2 adjacent-x voxels x CT couts.
// Accumulators are packed cout-pairs; weight pairs come from LDS.64 broadcast.
// ---------------------------------------------------------------------------
template <int CIN, int GIN, int GOUT, int STRIDE, int CT>
__global__ void conv_kernel(const float* __restrict__ in, const float* __restrict__ w,
                            const float* __restrict__ bias, const float* __restrict__ mout,
                            float* __restrict__ out, int cout_total) {
    extern __shared__ float ws[];   // 9*CIN*CT per kd slice
    const int cobase = blockIdx.y * CT;
    int tid = threadIdx.x;
    int pid = blockIdx.x * blockDim.x + tid;
    const int GX2 = GOUT / 2;
    int xp = pid % GX2; int t = pid / GX2;
    int yo = t % GOUT; t /= GOUT;
    int zo = t % GOUT; int b = t / GOUT;
    int x0 = xp * 2;

    size_t vox0 = ((size_t)(b * GOUT + zo) * GOUT + yo) * GOUT + x0;
    float m0 = mout[vox0], m1_ = mout[vox0 + 1];
    bool act = (m0 != 0.f) || (m1_ != 0.f);

    ull acc0[CT / 2], acc1[CT / 2];
#pragma unroll
    for (int p = 0; p < CT / 2; p++) { acc0[p] = 0ULL; acc1[p] = 0ULL; }

    for (int kd = 0; kd < 3; kd++) {
        __syncthreads();
        {
            const int n = 9 * CIN * CT;
            for (int j = tid; j < n; j += blockDim.x) {
                int co = j % CT;
                int rest = j / CT;             // khw*CIN + ci
                int ci = rest % CIN;
                int khw = rest / CIN;
                ws[j] = w[((size_t)(kd * 9 + khw) * CIN + ci) * cout_total + cobase + co];
            }
        }
        __syncthreads();

        int iz = zo * STRIDE + kd - 1;
        if (act && iz >= 0 && iz < GIN) {
            for (int kh = 0; kh < 3; kh++) {
                int iy = yo * STRIDE + kh - 1; if (iy < 0 || iy >= GIN) continue;
                size_t rowbase = ((size_t)(b * GIN + iz) * GIN + iy) * GIN;
                for (int kw = 0; kw < 3; kw++) {
                    int ix0 = x0 * STRIDE + kw - 1;
                    int ix1 = ix0 + STRIDE;
                    bool i0 = (ix0 >= 0) && (ix0 < GIN);
                    bool i1 = (ix1 >= 0) && (ix1 < GIN);
                    const float4* p04 = reinterpret_cast<const float4*>(in + (rowbase + (i0 ? ix0 : 0)) * CIN);
                    const float4* p14 = reinterpret_cast<const float4*>(in + (rowbase + (i1 ? ix1 : 0)) * CIN);
                    const float* wrow = ws + (kh * 3 + kw) * CIN * CT;
                    const float4 z4 = make_float4(0.f, 0.f, 0.f, 0.f);
#pragma unroll 2
                    for (int ci4 = 0; ci4 < CIN / 4; ci4++) {
                        float4 a0 = i0 ? p04[ci4] : z4;
                        float4 a1 = i1 ? p14[ci4] : z4;
                        float av0[4] = {a0.x, a0.y, a0.z, a0.w};
                        float av1[4] = {a1.x, a1.y, a1.z, a1.w};
#pragma unroll
                        for (int j = 0; j < 4; j++) {
                            ull X0 = pack2(av0[j], av0[j]);
                            ull X1 = pack2(av1[j], av1[j]);
                            const ull* wr = reinterpret_cast<const ull*>(wrow + (ci4 * 4 + j) * CT);
#pragma unroll
                            for (int p = 0; p < CT / 2; p++) {
                                ull wp = wr[p];
                                acc0[p] = fma2(X0, wp, acc0[p]);
                                acc1[p] = fma2(X1, wp, acc1[p]);
                            }
                        }
                    }
                }
            }
        }
    }

    const float4 z4 = make_float4(0.f, 0.f, 0.f, 0.f);
    float4* o0 = reinterpret_cast<float4*>(out + vox0 * cout_total + cobase);
    float4* o1 = reinterpret_cast<float4*>(out + (vox0 + 1) * cout_total + cobase);
#pragma unroll
    for (int q = 0; q < CT / 4; q++) {
        float b0 = bias[cobase + q * 4 + 0], b1 = bias[cobase + q * 4 + 1];
        float b2 = bias[cobase + q * 4 + 2], b3 = bias[cobase + q * 4 + 3];
        float4 r0, r1;
        unpack2(acc0[q * 2 + 0], r0.x, r0.y); unpack2(acc0[q * 2 + 1], r0.z, r0.w);
        unpack2(acc1[q * 2 + 0], r1.x, r1.y); unpack2(acc1[q * 2 + 1], r1.z, r1.w);
        r0.x += b0; r0.y += b1; r0.z += b2; r0.w += b3;
        r1.x += b0; r1.y += b1; r1.z += b2; r1.w += b3;
        o0[q] = (m0 != 0.f) ? r0 : z4;
        o1[q] = (m1_ != 0.f) ? r1 : z4;
    }
}

// ---------------------------------------------------------------------------
// In-place AdaNorm + ReLU over the channel axis
// ---------------------------------------------------------------------------
template <int C>
__global__ void adanorm_kernel(float* __restrict__ h, const float* __restrict__ g, int nvox) {
    int i = blockIdx.x * blockDim.x + threadIdx.x;
    if (i >= nvox) return;
    float4* p = reinterpret_cast<float4*>(h + (size_t)i * C);
    float v[C];
#pragma unroll
    for (int q = 0; q < C / 4; q++) {
        float4 a = p[q];
        v[q * 4 + 0] = a.x; v[q * 4 + 1] = a.y; v[q * 4 + 2] = a.z; v[q * 4 + 3] = a.w;
    }
    float s = 0.f;
#pragma unroll
    for (int c = 0; c < C; c++) s += v[c];
    float mean = s * (1.f / C);
    float s2 = 0.f;
#pragma unroll
    for (int c = 0; c < C; c++) { float d = v[c] - mean; s2 += d * d; }
    float r = rsqrtf(s2 * (1.f / C) + EPS_);
#pragma unroll
    for (int q = 0; q < C / 4; q++) {
        float4 a;
        float xn;
        xn = (v[q * 4 + 0] - mean) * r; a.x = fmaxf(g[q * 4 + 0] * (1.f - KADA * xn) * xn, 0.f);
        xn = (v[q * 4 + 1] - mean) * r; a.y = fmaxf(g[q * 4 + 1] * (1.f - KADA * xn) * xn, 0.f);
        xn = (v[q * 4 + 2] - mean) * r; a.z = fmaxf(g[q * 4 + 2] * (1.f - KADA * xn) * xn, 0.f);
        xn = (v[q * 4 + 3] - mean) * r; a.w = fmaxf(g[q * 4 + 3] * (1.f - KADA * xn) * xn, 0.f);
        p[q] = a;
    }
}

// ---------------------------------------------------------------------------
// Global masked max pool -> d_pool[2][64]
// ---------------------------------------------------------------------------
__global__ void pool_kernel() {
    int b = blockIdx.x;
    int c = threadIdx.x & 63;
    int grp = threadIdx.x >> 6;
    float best = -3.0e38f;
    for (int v = grp; v < 13824; v += 16) {
        float m = d_m3[b * 13824 + v];
        float hv = d_h5[((size_t)(b * 13824 + v)) * 64 + c];
        best = fmaxf(best, m > 0.f ? hv : -3.0e38f);
    }
    __shared__ float red[1024];
    red[threadIdx.x] = best;
    __syncthreads();
    for (int s = 8; s > 0; s >>= 1) {
        if (grp < s) red[grp * 64 + c] = fmaxf(red[grp * 64 + c], red[(grp + s) * 64 + c]);
        __syncthreads();
    }
    if (grp == 0) d_pool[b * 64 + c] = red[c];
}

// ---------------------------------------------------------------------------
// Head
// ---------------------------------------------------------------------------
__global__ void head_kernel(const float* __restrict__ wh, const float* __restrict__ bh,
                            const float* __restrict__ gh, float* __restrict__ out) {
    int t = threadIdx.x;
    int b = t >> 6;
    int f = t & 63;
    float s = bh[f];
    for (int ci = 0; ci < 64; ci++) s += d_pool[b * 64 + ci] * wh[ci * 64 + f];
    __shared__ float sh[128];
    sh[t] = s;
    __syncthreads();
    float sum = 0.f;
    for (int j = 0; j < 64; j++) sum += sh[b * 64 + j];
    float mean = sum * (1.f / 64.f);
    float var = 0.f;
    for (int j = 0; j < 64; j++) { float d = sh[b * 64 + j] - mean; var += d * d; }
    float r = rsqrtf(var * (1.f / 64.f) + EPS_);
    float xn = (s - mean) * r;
    out[t] = fmaxf(gh[f] * (1.f - KADA * xn) * xn, 0.f);
}

// ---------------------------------------------------------------------------
// Launch
// ---------------------------------------------------------------------------
extern "C" void kernel_launch(void* const* d_in, const int* in_sizes, int n_in,
                              void* d_out, int out_size) {
    const float* x    = (const float*)d_in[0];
    const float* mask = (const float*)d_in[1];
    const float* w1 = (const float*)d_in[2];
    const float* b1 = (const float*)d_in[3];
    const float* g1 = (const float*)d_in[4];
    const float* w2 = (const float*)d_in[5];
    const float* b2 = (const float*)d_in[6];
    const float* g2 = (const float*)d_in[7];
    const float* w3 = (const float*)d_in[8];
    const float* b3 = (const float*)d_in[9];
    const float* g3 = (const float*)d_in[10];
    const float* w4 = (const float*)d_in[11];
    const float* b4 = (const float*)d_in[12];
    const float* g4 = (const float*)d_in[13];
    const float* w5 = (const float*)d_in[14];
    const float* b5 = (const float*)d_in[15];
    const float* g5 = (const float*)d_in[16];
    const float* wh = (const float*)d_in[17];
    const float* bh = (const float*)d_in[18];
    const float* gh = (const float*)d_in[19];
    float* out = (float*)d_out;

    cudaFuncSetAttribute(l2_kernel, cudaFuncAttributeMaxDynamicSharedMemorySize, 56 * 1024);

    void *ph2, *ph3, *ph4, *ph5, *pm2, *pm3;
    cudaGetSymbolAddress(&ph2, d_h2);
    cudaGetSymbolAddress(&ph3, d_h3);
    cudaGetSymbolAddress(&ph4, d_h4);
    cudaGetSymbolAddress(&ph5, d_h5);
    cudaGetSymbolAddress(&pm2, d_m2);
    cudaGetSymbolAddress(&pm3, d_m3);

    // masks
    downsample_kernel<96, 48><<<(2 * 48 * 48 * 48 + 255) / 256, 256>>>(mask, (float*)pm2);
    downsample_kernel<48, 24><<<(2 * 24 * 24 * 24 + 255) / 256, 256>>>((const float*)pm2, (float*)pm3);

    // layer 1 (fused; active sites only)
    l1_kernel<<<2 * 96 * 96 * 96 / 128, 128>>>(x, mask, w1, b1, g1);

    // layer 2 (fused, ballot tap discovery)
    l2_kernel<<<592, 256, (13824 + 64) * 4>>>(mask, w2, b2, g2);

    // layer 3: 48^3, 32->32, s=1, CT=32, 128-thread blocks, 864 blocks
    conv_kernel<32, 48, 48, 1, 32><<<dim3(864, 1), 128, 9 * 32 * 32 * 4>>>(
        (const float*)ph2, w3, b3, (const float*)pm2, (float*)ph3, 32);
    adanorm_kernel<32><<<(2 * 48 * 48 * 48 + 255) / 256, 256>>>((float*)ph3, g3, 2 * 48 * 48 * 48);

    // layer 4: 48^3 -> 24^3, 32->64, s=2, CT=16, 64-thread blocks, 216x4 blocks
    conv_kernel<32, 48, 24, 2, 16><<<dim3(216, 4), 64, 9 * 32 * 16 * 4>>>(
        (const float*)ph3, w4, b4, (const float*)pm3, (float*)ph4, 64);
    adanorm_kernel<64><<<108, 256>>>((float*)ph4, g4, 2 * 24 * 24 * 24);

    // layer 5: 24^3, 64->64, s=1, CT=16, 64-thread blocks, 216x4 blocks
    conv_kernel<64, 24, 24, 1, 16><<<dim3(216, 4), 64, 9 * 64 * 16 * 4>>>(
        (const float*)ph4, w5, b5, (const float*)pm3, (float*)ph5, 64);
    adanorm_kernel<64><<<108, 256>>>((float*)ph5, g5, 2 * 24 * 24 * 24);

    // pool + head
    pool_kernel<<<2, 1024>>>();
    head_kernel<<<1, 128>>>(wh, bh, gh, out);
}